// round 7
// baseline (speedup 1.0000x reference)
#include <cuda_runtime.h>
#include <cuda_bf16.h>
#include <cstdint>

#define B_ 2
#define L_ 4096
#define H_ 1024

typedef __nv_bfloat16 bf16;

// ---------------- scratch (__device__ globals; no runtime alloc) ------------
__device__ bf16 g_h_hi [B_ * L_ * H_];   // RoPE'd h, bf16 hi   [B][L][H]
__device__ bf16 g_h_lo [B_ * L_ * H_];   // residual lo
__device__ bf16 g_hT_hi[B_ * H_ * L_];   // h transposed        [B][H][L]
__device__ bf16 g_hT_lo[B_ * H_ * L_];
__device__ bf16 g_WT_hi[H_ * H_];        // W^T (rows = cols of W)
__device__ bf16 g_WT_lo[H_ * H_];
__device__ bf16 g_G_hi [B_ * H_ * H_];   // G = h^T h (symmetric)
__device__ bf16 g_G_lo [B_ * H_ * H_];
__device__ bf16 g_MT_hi[B_ * H_ * H_];   // M^T = G W
__device__ bf16 g_MT_lo[B_ * H_ * H_];

// ---------------- helpers ---------------------------------------------------
__device__ __forceinline__ uint32_t smem_u32(const void* p) {
    uint32_t a;
    asm("{ .reg .u64 t; cvta.to.shared.u64 t, %1; cvt.u32.u64 %0, t; }" : "=r"(a) : "l"(p));
    return a;
}
__device__ __forceinline__ void cp16(uint32_t saddr, const void* gaddr) {
    asm volatile("cp.async.cg.shared.global [%0], [%1], 16;" :: "r"(saddr), "l"(gaddr));
}
__device__ __forceinline__ void cp_commit() {
    asm volatile("cp.async.commit_group;" ::: "memory");
}
__device__ __forceinline__ void cp_wait1() {
    asm volatile("cp.async.wait_group 1;" ::: "memory");
}
__device__ __forceinline__ void ldsm4(uint32_t* r, uint32_t addr) {
    asm volatile("ldmatrix.sync.aligned.m8n8.x4.shared.b16 {%0,%1,%2,%3}, [%4];"
                 : "=r"(r[0]), "=r"(r[1]), "=r"(r[2]), "=r"(r[3]) : "r"(addr));
}
__device__ __forceinline__ void mma16816(float* c, const uint32_t* a, const uint32_t* b) {
    asm volatile(
        "mma.sync.aligned.m16n8k16.row.col.f32.bf16.bf16.f32 "
        "{%0,%1,%2,%3}, {%4,%5,%6,%7}, {%8,%9}, {%0,%1,%2,%3};"
        : "+f"(c[0]), "+f"(c[1]), "+f"(c[2]), "+f"(c[3])
        : "r"(a[0]), "r"(a[1]), "r"(a[2]), "r"(a[3]), "r"(b[0]), "r"(b[1]));
}

// ---------------- fused RoPE + split + transpose ----------------------------
// One pass over x: writes hh/hl [B][L][H] and hth/htl [B][H][L].
// Tile 64(l) x 64(h); rotate-half partner block is h0 +/- 512 (64-aligned).
__global__ void rope_split_t(const float* __restrict__ x,
                             const float* __restrict__ cs,
                             const float* __restrict__ sn,
                             bf16* __restrict__ hh, bf16* __restrict__ hl,
                             bf16* __restrict__ hth, bf16* __restrict__ htl) {
    __shared__ bf16 thi[64][66];
    __shared__ bf16 tlo[64][66];
    const int b  = blockIdx.z;
    const int l0 = blockIdx.x * 64;
    const int h0 = blockIdx.y * 64;
    const int tx = threadIdx.x, ty = threadIdx.y;     // 32 x 8
    const long base = (long)b * L_ * H_;
    const int ph0 = (h0 < H_ / 2) ? h0 + H_ / 2 : h0 - H_ / 2;
    const float sgn = (h0 < H_ / 2) ? -1.f : 1.f;
    const int c = 2 * tx;

#pragma unroll
    for (int i = 0; i < 8; i++) {
        int r = ty + 8 * i;
        long l = l0 + r;
        float2 xv = *(const float2*)(x + base + l * H_ + h0 + c);
        float2 pv = *(const float2*)(x + base + l * H_ + ph0 + c);
        float2 cv = *(const float2*)(cs + l * H_ + h0 + c);
        float2 sv = *(const float2*)(sn + l * H_ + h0 + c);
        float o0 = xv.x * cv.x + sgn * pv.x * sv.x;
        float o1 = xv.y * cv.y + sgn * pv.y * sv.y;
        bf16 hi0 = __float2bfloat16_rn(o0);
        bf16 hi1 = __float2bfloat16_rn(o1);
        bf16 lo0 = __float2bfloat16_rn(o0 - __bfloat162float(hi0));
        bf16 lo1 = __float2bfloat16_rn(o1 - __bfloat162float(hi1));
        *(__nv_bfloat162*)(hh + base + l * H_ + h0 + c) = __nv_bfloat162(hi0, hi1);
        *(__nv_bfloat162*)(hl + base + l * H_ + h0 + c) = __nv_bfloat162(lo0, lo1);
        thi[r][c] = hi0; thi[r][c + 1] = hi1;
        tlo[r][c] = lo0; tlo[r][c + 1] = lo1;
    }
    __syncthreads();
#pragma unroll
    for (int i = 0; i < 8; i++) {
        int r = ty + 8 * i;                 // h-row within tile
        long row = h0 + r;
        *(__nv_bfloat162*)(hth + base + row * L_ + l0 + c) =
            __nv_bfloat162(thi[c][r], thi[c + 1][r]);
        *(__nv_bfloat162*)(htl + base + row * L_ + l0 + c) =
            __nv_bfloat162(tlo[c][r], tlo[c + 1][r]);
    }
}

// ---------------- W split + transpose --------------------------------------
__global__ void wsplit_t(const float* __restrict__ W, bf16* __restrict__ wth,
                         bf16* __restrict__ wtl) {
    long e = (long)blockIdx.x * blockDim.x + threadIdx.x;
    int o = (int)(e >> 10), c = (int)(e & (H_ - 1));
    float v = W[e];
    bf16 hi = __float2bfloat16_rn(v);
    bf16 lo = __float2bfloat16_rn(v - __bfloat162float(hi));
    wth[(long)c * H_ + o] = hi;   // wth[n][k] = W[k][n]
    wtl[(long)c * H_ + o] = lo;
}

// ---------------- HMMA split-bf16 GEMM --------------------------------------
// C[m][n] = sum_k A[m][k]*B[n][k] with split accumulation
//   acc += Ah*Bh + Ah*Bl + Al*Bh   (lo*lo dropped, ~2^-18)
// CTA tile 128x128, BK=64, 8 warps (warp tile 32x64), 3-stage cp.async.
// Fragments double-buffered across k16 slices: ldmatrix for slice ks+1 issues
// before the MMA burst of slice ks, hiding LDSM latency/port time under MMA.
#define PITCH    144                      // bytes per smem row (64 bf16 + 16 pad)
#define TILE_B   (128 * PITCH)            // 18432 B per operand tile
#define STAGE_B  (4 * TILE_B)             // Ah, Al, Bh, Bl = 73728 B
#define NSTAGE   3
#define SMEM_BYTES (NSTAGE * STAGE_B)     // 221184 B

__global__ __launch_bounds__(256, 1)
void gemm_mma(const bf16* __restrict__ Ah, const bf16* __restrict__ Al,
              const bf16* __restrict__ Bh, const bf16* __restrict__ Bl,
              float* __restrict__ Cf, bf16* __restrict__ Ch, bf16* __restrict__ Cl,
              int K, int lda, int ldb, int ldc,
              long sA, long sB, long sC, int split_out) {
    extern __shared__ char sm[];
    const uint32_t sb = smem_u32(sm);

    const int tid  = threadIdx.x;
    const int wid  = tid >> 5;
    const int lane = tid & 31;
    const int bz   = blockIdx.z;
    const long m0  = (long)blockIdx.y * 128;
    const long n0  = (long)blockIdx.x * 128;

    const int warp_m = (wid >> 1) * 32;
    const int warp_n = (wid & 1) * 64;

    const bf16* gbase[4];
    gbase[0] = Ah + bz * sA + m0 * lda;
    gbase[1] = Al + bz * sA + m0 * lda;
    gbase[2] = Bh + bz * sB + n0 * ldb;
    gbase[3] = Bl + bz * sB + n0 * ldb;

    // per-thread cp.async mapping: 16 chunks of 16B per stage
    long c_goff[16];
    uint32_t c_soff[16];
    int c_tile[16];
#pragma unroll
    for (int i = 0; i < 16; i++) {
        int t = tid + i * 256;
        int tile = t >> 10;
        int row  = (t >> 3) & 127;
        int ci   = t & 7;
        int ld   = (tile < 2) ? lda : ldb;
        c_tile[i] = tile;
        c_goff[i] = (long)row * ld + ci * 8;
        c_soff[i] = (uint32_t)(tile * TILE_B + row * PITCH + ci * 16);
    }

    auto load_stage = [&](int it) {
        int st = it % NSTAGE;
        long k0 = (long)it * 64;
        uint32_t sbase = sb + st * STAGE_B;
#pragma unroll
        for (int i = 0; i < 16; i++)
            cp16(sbase + c_soff[i], gbase[c_tile[i]] + k0 + c_goff[i]);
        cp_commit();
    };

    float acc[2][8][4];
#pragma unroll
    for (int mt = 0; mt < 2; mt++)
#pragma unroll
        for (int j = 0; j < 8; j++)
#pragma unroll
            for (int q = 0; q < 4; q++) acc[mt][j][q] = 0.f;

    const int nIter = K >> 6;
    load_stage(0);
    load_stage(1);

    const int a_rowoff = (lane & 7) + ((lane >> 3) & 1) * 8;
    const int a_choff  = (lane >> 4);
    const int b_rowoff = ((lane >> 4) & 1) * 8 + (lane & 7);
    const int b_choff  = ((lane >> 3) & 1);

    // double-buffered fragments
    uint32_t ah[2][2][4], al[2][2][4], bh[2][4][4], bl[2][4][4];

    for (int it = 0; it < nIter; it++) {
        cp_wait1();
        __syncthreads();
        if (it + 2 < nIter) load_stage(it + 2);

        uint32_t sbase = sb + (it % NSTAGE) * STAGE_B;
        uint32_t sAh = sbase;
        uint32_t sAl = sbase + TILE_B;
        uint32_t sBh = sbase + 2 * TILE_B;
        uint32_t sBl = sbase + 3 * TILE_B;

        // preload slice 0 into buffer 0
#pragma unroll
        for (int mt = 0; mt < 2; mt++) {
            uint32_t off = (uint32_t)((warp_m + mt * 16 + a_rowoff) * PITCH
                                      + a_choff * 16);
            ldsm4(ah[0][mt], sAh + off);
            ldsm4(al[0][mt], sAl + off);
        }
#pragma unroll
        for (int jp = 0; jp < 4; jp++) {
            uint32_t off = (uint32_t)((warp_n + jp * 16 + b_rowoff) * PITCH
                                      + b_choff * 16);
            ldsm4(bh[0][jp], sBh + off);
            ldsm4(bl[0][jp], sBl + off);
        }

#pragma unroll
        for (int ks = 0; ks < 4; ks++) {
            const int cur = ks & 1, nxt = cur ^ 1;
            if (ks < 3) {
                const int kc = (ks + 1) * 2;
#pragma unroll
                for (int mt = 0; mt < 2; mt++) {
                    uint32_t off = (uint32_t)((warp_m + mt * 16 + a_rowoff) * PITCH
                                              + (kc + a_choff) * 16);
                    ldsm4(ah[nxt][mt], sAh + off);
                    ldsm4(al[nxt][mt], sAl + off);
                }
#pragma unroll
                for (int jp = 0; jp < 4; jp++) {
                    uint32_t off = (uint32_t)((warp_n + jp * 16 + b_rowoff) * PITCH
                                              + (kc + b_choff) * 16);
                    ldsm4(bh[nxt][jp], sBh + off);
                    ldsm4(bl[nxt][jp], sBl + off);
                }
            }
            // 96 MMAs on current buffer; accumulator reuse spread 32 apart
#pragma unroll
            for (int p = 0; p < 3; p++) {
#pragma unroll
                for (int jp = 0; jp < 4; jp++) {
#pragma unroll
                    for (int mt = 0; mt < 2; mt++) {
                        const uint32_t* av = (p == 2) ? al[cur][mt] : ah[cur][mt];
                        const uint32_t* bv = (p == 1) ? bl[cur][jp] : bh[cur][jp];
                        mma16816(acc[mt][2 * jp],     av, bv);
                        mma16816(acc[mt][2 * jp + 1], av, bv + 2);
                    }
                }
            }
        }
    }

    // ---------------- epilogue ----------------
    const int r_lo = lane >> 2;
    const int c_lo = 2 * (lane & 3);
#pragma unroll
    for (int mt = 0; mt < 2; mt++) {
#pragma unroll
        for (int j = 0; j < 8; j++) {
            long row = m0 + warp_m + mt * 16 + r_lo;
            long col = n0 + warp_n + j * 8 + c_lo;
            float v0 = acc[mt][j][0], v1 = acc[mt][j][1];
            float v2 = acc[mt][j][2], v3 = acc[mt][j][3];
            if (!split_out) {
                float* p = Cf + bz * sC;
                *(float2*)(p + row * ldc + col)       = make_float2(v0, v1);
                *(float2*)(p + (row + 8) * ldc + col) = make_float2(v2, v3);
            } else {
                bf16 h0 = __float2bfloat16_rn(v0);
                bf16 h1 = __float2bfloat16_rn(v1);
                bf16 h2 = __float2bfloat16_rn(v2);
                bf16 h3 = __float2bfloat16_rn(v3);
                bf16 l0 = __float2bfloat16_rn(v0 - __bfloat162float(h0));
                bf16 l1 = __float2bfloat16_rn(v1 - __bfloat162float(h1));
                bf16 l2 = __float2bfloat16_rn(v2 - __bfloat162float(h2));
                bf16 l3 = __float2bfloat16_rn(v3 - __bfloat162float(h3));
                long o0 = bz * sC + row * ldc + col;
                long o1 = bz * sC + (row + 8) * ldc + col;
                *(__nv_bfloat162*)(Ch + o0) = __nv_bfloat162(h0, h1);
                *(__nv_bfloat162*)(Ch + o1) = __nv_bfloat162(h2, h3);
                *(__nv_bfloat162*)(Cl + o0) = __nv_bfloat162(l0, l1);
                *(__nv_bfloat162*)(Cl + o1) = __nv_bfloat162(l2, l3);
            }
        }
    }
}

// ---------------- launch ----------------------------------------------------
extern "C" void kernel_launch(void* const* d_in, const int* in_sizes, int n_in,
                              void* d_out, int out_size) {
    const float* x  = (const float*)d_in[0];
    const float* W  = (const float*)d_in[1];
    const float* cs = (const float*)d_in[2];
    const float* sn = (const float*)d_in[3];
    float* out = (float*)d_out;

    void *p0, *p1, *p2, *p3, *p4, *p5, *p6, *p7, *p8, *p9;
    cudaGetSymbolAddress(&p0, g_h_hi);  cudaGetSymbolAddress(&p1, g_h_lo);
    cudaGetSymbolAddress(&p2, g_hT_hi); cudaGetSymbolAddress(&p3, g_hT_lo);
    cudaGetSymbolAddress(&p4, g_WT_hi); cudaGetSymbolAddress(&p5, g_WT_lo);
    cudaGetSymbolAddress(&p6, g_G_hi);  cudaGetSymbolAddress(&p7, g_G_lo);
    cudaGetSymbolAddress(&p8, g_MT_hi); cudaGetSymbolAddress(&p9, g_MT_lo);
    bf16 *hh = (bf16*)p0, *hl = (bf16*)p1, *hth = (bf16*)p2, *htl = (bf16*)p3;
    bf16 *wth = (bf16*)p4, *wtl = (bf16*)p5, *Gh = (bf16*)p6, *Gl = (bf16*)p7;
    bf16 *MTh = (bf16*)p8, *MTl = (bf16*)p9;

    cudaFuncSetAttribute(gemm_mma, cudaFuncAttributeMaxDynamicSharedMemorySize,
                         SMEM_BYTES);

    const long HL = (long)H_ * L_;
    const long HH = (long)H_ * H_;

    // 1) fused RoPE + split + transpose
    rope_split_t<<<dim3(L_ / 64, H_ / 64, B_), dim3(32, 8)>>>(
        x, cs, sn, hh, hl, hth, htl);

    // 2) W split + transpose
    wsplit_t<<<(H_ * H_) / 256, 256>>>(W, wth, wtl);

    // 3) G = h^T h : A=B=hT [H][L], K=L -> G (bf16 split, symmetric)
    gemm_mma<<<dim3(H_ / 128, H_ / 128, B_), 256, SMEM_BYTES>>>(
        hth, htl, hth, htl, nullptr, Gh, Gl, L_, L_, L_, H_, HL, HL, HH, 1);

    // 4) M^T = G W : A=G [H][H], B=W^T [n][k], K=H -> MT (bf16 split)
    gemm_mma<<<dim3(H_ / 128, H_ / 128, B_), 256, SMEM_BYTES>>>(
        Gh, Gl, wth, wtl, nullptr, MTh, MTl, H_, H_, H_, H_, HH, 0, HH, 1);

    // 5) out = h M : A=h [L][H], B=MT [n][k], K=H -> fp32 out
    gemm_mma<<<dim3(H_ / 128, L_ / 128, B_), 256, SMEM_BYTES>>>(
        hh, hl, MTh, MTl, out, nullptr, nullptr, H_, H_, H_, H_, HL, HH, HL, 0);
}

// round 8
// speedup vs baseline: 1.2147x; 1.2147x over previous
#include <cuda_runtime.h>
#include <cuda_bf16.h>
#include <cstdint>

#define B_ 2
#define L_ 4096
#define H_ 1024

typedef __nv_bfloat16 bf16;

// ---------------- scratch (__device__ globals; no runtime alloc) ------------
__device__ bf16  g_h_hi [B_ * L_ * H_];   // RoPE'd h, bf16 hi   [B][L][H]
__device__ bf16  g_h_lo [B_ * L_ * H_];   // residual lo
__device__ bf16  g_hT_hi[B_ * H_ * L_];   // h transposed        [B][H][L]
__device__ bf16  g_hT_lo[B_ * H_ * L_];
__device__ bf16  g_WT_hi[H_ * H_];        // W^T (rows = cols of W)
__device__ bf16  g_WT_lo[H_ * H_];
__device__ bf16  g_G_hi [B_ * H_ * H_];   // G = h^T h (symmetric)
__device__ bf16  g_G_lo [B_ * H_ * H_];
__device__ bf16  g_MT_hi[B_ * H_ * H_];   // M^T = G W
__device__ bf16  g_MT_lo[B_ * H_ * H_];
__device__ float g_Gp  [B_ * 2 * H_ * H_]; // split-K partials for G (fp32)

// upper-triangle tile LUT for 8x8 tile grid (36 unique tiles)
__device__ const int TI_LUT[36] = {0,0,0,0,0,0,0,0, 1,1,1,1,1,1,1, 2,2,2,2,2,2,
                                   3,3,3,3,3, 4,4,4,4, 5,5,5, 6,6, 7};
__device__ const int TJ_LUT[36] = {0,1,2,3,4,5,6,7, 1,2,3,4,5,6,7, 2,3,4,5,6,7,
                                   3,4,5,6,7, 4,5,6,7, 5,6,7, 6,7, 7};

// ---------------- helpers ---------------------------------------------------
__device__ __forceinline__ uint32_t smem_u32(const void* p) {
    uint32_t a;
    asm("{ .reg .u64 t; cvta.to.shared.u64 t, %1; cvt.u32.u64 %0, t; }" : "=r"(a) : "l"(p));
    return a;
}
__device__ __forceinline__ void cp16(uint32_t saddr, const void* gaddr) {
    asm volatile("cp.async.cg.shared.global [%0], [%1], 16;" :: "r"(saddr), "l"(gaddr));
}
__device__ __forceinline__ void cp_commit() {
    asm volatile("cp.async.commit_group;" ::: "memory");
}
__device__ __forceinline__ void cp_wait1() {
    asm volatile("cp.async.wait_group 1;" ::: "memory");
}
__device__ __forceinline__ void ldsm4(uint32_t* r, uint32_t addr) {
    asm volatile("ldmatrix.sync.aligned.m8n8.x4.shared.b16 {%0,%1,%2,%3}, [%4];"
                 : "=r"(r[0]), "=r"(r[1]), "=r"(r[2]), "=r"(r[3]) : "r"(addr));
}
__device__ __forceinline__ void mma16816(float* c, const uint32_t* a, const uint32_t* b) {
    asm volatile(
        "mma.sync.aligned.m16n8k16.row.col.f32.bf16.bf16.f32 "
        "{%0,%1,%2,%3}, {%4,%5,%6,%7}, {%8,%9}, {%0,%1,%2,%3};"
        : "+f"(c[0]), "+f"(c[1]), "+f"(c[2]), "+f"(c[3])
        : "r"(a[0]), "r"(a[1]), "r"(a[2]), "r"(a[3]), "r"(b[0]), "r"(b[1]));
}

// ---------------- fused RoPE + split + transpose ----------------------------
__global__ void rope_split_t(const float* __restrict__ x,
                             const float* __restrict__ cs,
                             const float* __restrict__ sn,
                             bf16* __restrict__ hh, bf16* __restrict__ hl,
                             bf16* __restrict__ hth, bf16* __restrict__ htl) {
    __shared__ bf16 thi[64][66];
    __shared__ bf16 tlo[64][66];
    const int b  = blockIdx.z;
    const int l0 = blockIdx.x * 64;
    const int h0 = blockIdx.y * 64;
    const int tx = threadIdx.x, ty = threadIdx.y;     // 32 x 8
    const long base = (long)b * L_ * H_;
    const int ph0 = (h0 < H_ / 2) ? h0 + H_ / 2 : h0 - H_ / 2;
    const float sgn = (h0 < H_ / 2) ? -1.f : 1.f;
    const int c = 2 * tx;

#pragma unroll
    for (int i = 0; i < 8; i++) {
        int r = ty + 8 * i;
        long l = l0 + r;
        float2 xv = *(const float2*)(x + base + l * H_ + h0 + c);
        float2 pv = *(const float2*)(x + base + l * H_ + ph0 + c);
        float2 cv = *(const float2*)(cs + l * H_ + h0 + c);
        float2 sv = *(const float2*)(sn + l * H_ + h0 + c);
        float o0 = xv.x * cv.x + sgn * pv.x * sv.x;
        float o1 = xv.y * cv.y + sgn * pv.y * sv.y;
        bf16 hi0 = __float2bfloat16_rn(o0);
        bf16 hi1 = __float2bfloat16_rn(o1);
        bf16 lo0 = __float2bfloat16_rn(o0 - __bfloat162float(hi0));
        bf16 lo1 = __float2bfloat16_rn(o1 - __bfloat162float(hi1));
        *(__nv_bfloat162*)(hh + base + l * H_ + h0 + c) = __nv_bfloat162(hi0, hi1);
        *(__nv_bfloat162*)(hl + base + l * H_ + h0 + c) = __nv_bfloat162(lo0, lo1);
        thi[r][c] = hi0; thi[r][c + 1] = hi1;
        tlo[r][c] = lo0; tlo[r][c + 1] = lo1;
    }
    __syncthreads();
#pragma unroll
    for (int i = 0; i < 8; i++) {
        int r = ty + 8 * i;
        long row = h0 + r;
        *(__nv_bfloat162*)(hth + base + row * L_ + l0 + c) =
            __nv_bfloat162(thi[c][r], thi[c + 1][r]);
        *(__nv_bfloat162*)(htl + base + row * L_ + l0 + c) =
            __nv_bfloat162(tlo[c][r], tlo[c + 1][r]);
    }
}

// ---------------- W split + transpose --------------------------------------
__global__ void wsplit_t(const float* __restrict__ W, bf16* __restrict__ wth,
                         bf16* __restrict__ wtl) {
    long e = (long)blockIdx.x * blockDim.x + threadIdx.x;
    int o = (int)(e >> 10), c = (int)(e & (H_ - 1));
    float v = W[e];
    bf16 hi = __float2bfloat16_rn(v);
    bf16 lo = __float2bfloat16_rn(v - __bfloat162float(hi));
    wth[(long)c * H_ + o] = hi;
    wtl[(long)c * H_ + o] = lo;
}

// ---------------- HMMA split-bf16 GEMM (R6 core + triangular split-K) -------
// C[m][n] = sum_k A[m][k]*B[n][k];  acc += Ah*Bh + Ah*Bl + Al*Bh
// CTA tile 128x128, BK=64, 16 warps (warp tile 32x32), 3-stage cp.async.
// tri=1: blockIdx.x encodes (uppertile t, k-half ks); fp32 partial out.
#define PITCH    144
#define TILE_B   (128 * PITCH)
#define STAGE_B  (4 * TILE_B)
#define NSTAGE   3
#define SMEM_BYTES (NSTAGE * STAGE_B)     // 221184 B

__global__ __launch_bounds__(512, 1)
void gemm_mma(const bf16* __restrict__ Ah, const bf16* __restrict__ Al,
              const bf16* __restrict__ Bh, const bf16* __restrict__ Bl,
              float* __restrict__ Cf, bf16* __restrict__ Ch, bf16* __restrict__ Cl,
              int K, int lda, int ldb, int ldc,
              long sA, long sB, long sC, int split_out, int tri) {
    extern __shared__ char sm[];
    const uint32_t sb = smem_u32(sm);

    const int tid  = threadIdx.x;
    const int wid  = tid >> 5;
    const int lane = tid & 31;
    const int bz   = blockIdx.z;

    long m0, n0, cofs;
    int i0, i1;
    if (tri) {
        int t  = blockIdx.x >> 1;
        int ks = blockIdx.x & 1;
        m0 = (long)TI_LUT[t] * 128;
        n0 = (long)TJ_LUT[t] * 128;
        int kh = K >> 1;
        i0 = (ks * kh) >> 6;
        i1 = i0 + (kh >> 6);
        cofs = (long)(bz * 2 + ks) * sC;
    } else {
        m0 = (long)blockIdx.y * 128;
        n0 = (long)blockIdx.x * 128;
        i0 = 0;
        i1 = K >> 6;
        cofs = (long)bz * sC;
    }

    const int warp_m = (wid >> 2) * 32;
    const int warp_n = (wid & 3) * 32;

    const bf16* gbase[4];
    gbase[0] = Ah + bz * sA + m0 * lda;
    gbase[1] = Al + bz * sA + m0 * lda;
    gbase[2] = Bh + bz * sB + n0 * ldb;
    gbase[3] = Bl + bz * sB + n0 * ldb;

    long c_goff[8];
    uint32_t c_soff[8];
    int c_tile[8];
#pragma unroll
    for (int i = 0; i < 8; i++) {
        int t = tid + i * 512;
        int tile = t >> 10;
        int row  = (t >> 3) & 127;
        int ci   = t & 7;
        int ld   = (tile < 2) ? lda : ldb;
        c_tile[i] = tile;
        c_goff[i] = (long)row * ld + ci * 8;
        c_soff[i] = (uint32_t)(tile * TILE_B + row * PITCH + ci * 16);
    }

    auto load_stage = [&](int it) {
        int st = it % NSTAGE;
        long k0 = (long)it * 64;
        uint32_t sbase = sb + st * STAGE_B;
#pragma unroll
        for (int i = 0; i < 8; i++)
            cp16(sbase + c_soff[i], gbase[c_tile[i]] + k0 + c_goff[i]);
        cp_commit();
    };

    float acc[2][4][4];
#pragma unroll
    for (int mt = 0; mt < 2; mt++)
#pragma unroll
        for (int j = 0; j < 4; j++)
#pragma unroll
            for (int q = 0; q < 4; q++) acc[mt][j][q] = 0.f;

    load_stage(i0);
    load_stage(i0 + 1);

    const int a_rowoff = (lane & 7) + ((lane >> 3) & 1) * 8;
    const int a_choff  = (lane >> 4);
    const int b_rowoff = ((lane >> 4) & 1) * 8 + (lane & 7);
    const int b_choff  = ((lane >> 3) & 1);

    for (int it = i0; it < i1; it++) {
        cp_wait1();
        __syncthreads();
        if (it + 2 < i1) load_stage(it + 2);

        uint32_t sbase = sb + (it % NSTAGE) * STAGE_B;
        uint32_t sAh = sbase;
        uint32_t sAl = sbase + TILE_B;
        uint32_t sBh = sbase + 2 * TILE_B;
        uint32_t sBl = sbase + 3 * TILE_B;

#pragma unroll
        for (int ks = 0; ks < 4; ks++) {
            const int kc = ks * 2;
            uint32_t ah[2][4], al[2][4], bh[2][4], bl[2][4];
#pragma unroll
            for (int mt = 0; mt < 2; mt++) {
                uint32_t off = (uint32_t)((warp_m + mt * 16 + a_rowoff) * PITCH
                                          + (kc + a_choff) * 16);
                ldsm4(ah[mt], sAh + off);
                ldsm4(al[mt], sAl + off);
            }
#pragma unroll
            for (int jp = 0; jp < 2; jp++) {
                uint32_t off = (uint32_t)((warp_n + jp * 16 + b_rowoff) * PITCH
                                          + (kc + b_choff) * 16);
                ldsm4(bh[jp], sBh + off);
                ldsm4(bl[jp], sBl + off);
            }
#pragma unroll
            for (int p = 0; p < 3; p++) {
#pragma unroll
                for (int jp = 0; jp < 2; jp++) {
#pragma unroll
                    for (int mt = 0; mt < 2; mt++) {
                        const uint32_t* av = (p == 2) ? al[mt] : ah[mt];
                        const uint32_t* bv = (p == 1) ? bl[jp] : bh[jp];
                        mma16816(acc[mt][2 * jp],     av, bv);
                        mma16816(acc[mt][2 * jp + 1], av, bv + 2);
                    }
                }
            }
        }
    }

    // ---------------- epilogue ----------------
    const int r_lo = lane >> 2;
    const int c_lo = 2 * (lane & 3);
#pragma unroll
    for (int mt = 0; mt < 2; mt++) {
#pragma unroll
        for (int j = 0; j < 4; j++) {
            long row = m0 + warp_m + mt * 16 + r_lo;
            long col = n0 + warp_n + j * 8 + c_lo;
            float v0 = acc[mt][j][0], v1 = acc[mt][j][1];
            float v2 = acc[mt][j][2], v3 = acc[mt][j][3];
            if (!split_out) {
                float* p = Cf + cofs;
                *(float2*)(p + row * ldc + col)       = make_float2(v0, v1);
                *(float2*)(p + (row + 8) * ldc + col) = make_float2(v2, v3);
            } else {
                bf16 h0 = __float2bfloat16_rn(v0);
                bf16 h1 = __float2bfloat16_rn(v1);
                bf16 h2 = __float2bfloat16_rn(v2);
                bf16 h3 = __float2bfloat16_rn(v3);
                bf16 l0 = __float2bfloat16_rn(v0 - __bfloat162float(h0));
                bf16 l1 = __float2bfloat16_rn(v1 - __bfloat162float(h1));
                bf16 l2 = __float2bfloat16_rn(v2 - __bfloat162float(h2));
                bf16 l3 = __float2bfloat16_rn(v3 - __bfloat162float(h3));
                long o0 = cofs + row * ldc + col;
                long o1 = cofs + (row + 8) * ldc + col;
                *(__nv_bfloat162*)(Ch + o0) = __nv_bfloat162(h0, h1);
                *(__nv_bfloat162*)(Ch + o1) = __nv_bfloat162(h2, h3);
                *(__nv_bfloat162*)(Cl + o0) = __nv_bfloat162(l0, l1);
                *(__nv_bfloat162*)(Cl + o1) = __nv_bfloat162(l2, l3);
            }
        }
    }
}

// ---------------- G fixup: sum split-K partials, hi/lo split, mirror --------
// grid (36, 4, B_): tile t, 32-row chunk, batch. 256 threads.
__global__ void g_fixup(const float* __restrict__ Gp,
                        bf16* __restrict__ Gh, bf16* __restrict__ Gl) {
    __shared__ bf16 shi[32][132];
    __shared__ bf16 slo[32][132];
    const int t = blockIdx.x, b = blockIdx.z;
    const int ti = TI_LUT[t], tj = TJ_LUT[t];
    const long m0 = (long)ti * 128 + blockIdx.y * 32;
    const long n0 = (long)tj * 128;
    const long HH = (long)H_ * H_;
    const float* P0 = Gp + (long)(b * 2 + 0) * HH;
    const float* P1 = Gp + (long)(b * 2 + 1) * HH;
    bf16* gh = Gh + (long)b * HH;
    bf16* gl = Gl + (long)b * HH;

    const int tid = threadIdx.x;
    const int r   = tid >> 3;              // 0..31
    const int cs  = (tid & 7) * 16;        // 16 cols each

#pragma unroll
    for (int v4 = 0; v4 < 4; v4++) {
        int col = cs + v4 * 4;
        long off = (m0 + r) * H_ + n0 + col;
        float4 p0 = *(const float4*)(P0 + off);
        float4 p1 = *(const float4*)(P1 + off);
        float v[4] = {p0.x + p1.x, p0.y + p1.y, p0.z + p1.z, p0.w + p1.w};
        bf16 hi[4], lo[4];
#pragma unroll
        for (int q = 0; q < 4; q++) {
            hi[q] = __float2bfloat16_rn(v[q]);
            lo[q] = __float2bfloat16_rn(v[q] - __bfloat162float(hi[q]));
            shi[r][col + q] = hi[q];
            slo[r][col + q] = lo[q];
        }
        *(__nv_bfloat162*)(gh + off)     = __nv_bfloat162(hi[0], hi[1]);
        *(__nv_bfloat162*)(gh + off + 2) = __nv_bfloat162(hi[2], hi[3]);
        *(__nv_bfloat162*)(gl + off)     = __nv_bfloat162(lo[0], lo[1]);
        *(__nv_bfloat162*)(gl + off + 2) = __nv_bfloat162(lo[2], lo[3]);
    }

    if (ti == tj) return;   // mirror region identical to direct region
    __syncthreads();

    const int cc   = tid >> 1;             // 0..127 (source column)
    const int half = tid & 1;              // 16 rows each
    long moff = (n0 + cc) * H_ + m0 + half * 16;
#pragma unroll
    for (int k = 0; k < 8; k++) {
        int rr = half * 16 + 2 * k;
        *(__nv_bfloat162*)(gh + moff + 2 * k) = __nv_bfloat162(shi[rr][cc], shi[rr + 1][cc]);
        *(__nv_bfloat162*)(gl + moff + 2 * k) = __nv_bfloat162(slo[rr][cc], slo[rr + 1][cc]);
    }
}

// ---------------- launch ----------------------------------------------------
extern "C" void kernel_launch(void* const* d_in, const int* in_sizes, int n_in,
                              void* d_out, int out_size) {
    const float* x  = (const float*)d_in[0];
    const float* W  = (const float*)d_in[1];
    const float* cs = (const float*)d_in[2];
    const float* sn = (const float*)d_in[3];
    float* out = (float*)d_out;

    void *p0, *p1, *p2, *p3, *p4, *p5, *p6, *p7, *p8, *p9, *pGp;
    cudaGetSymbolAddress(&p0, g_h_hi);  cudaGetSymbolAddress(&p1, g_h_lo);
    cudaGetSymbolAddress(&p2, g_hT_hi); cudaGetSymbolAddress(&p3, g_hT_lo);
    cudaGetSymbolAddress(&p4, g_WT_hi); cudaGetSymbolAddress(&p5, g_WT_lo);
    cudaGetSymbolAddress(&p6, g_G_hi);  cudaGetSymbolAddress(&p7, g_G_lo);
    cudaGetSymbolAddress(&p8, g_MT_hi); cudaGetSymbolAddress(&p9, g_MT_lo);
    cudaGetSymbolAddress(&pGp, g_Gp);
    bf16 *hh = (bf16*)p0, *hl = (bf16*)p1, *hth = (bf16*)p2, *htl = (bf16*)p3;
    bf16 *wth = (bf16*)p4, *wtl = (bf16*)p5, *Gh = (bf16*)p6, *Gl = (bf16*)p7;
    bf16 *MTh = (bf16*)p8, *MTl = (bf16*)p9;
    float* Gp = (float*)pGp;

    cudaFuncSetAttribute(gemm_mma, cudaFuncAttributeMaxDynamicSharedMemorySize,
                         SMEM_BYTES);

    const long HL = (long)H_ * L_;
    const long HH = (long)H_ * H_;

    // 1) fused RoPE + split + transpose
    rope_split_t<<<dim3(L_ / 64, H_ / 64, B_), dim3(32, 8)>>>(
        x, cs, sn, hh, hl, hth, htl);

    // 2) W split + transpose
    wsplit_t<<<(H_ * H_) / 256, 256>>>(W, wth, wtl);

    // 3) G partials: upper-triangle tiles, split-K=2 (144 CTAs, 32 iters each)
    gemm_mma<<<dim3(72, 1, B_), 512, SMEM_BYTES>>>(
        hth, htl, hth, htl, Gp, nullptr, nullptr, L_, L_, L_, H_, HL, HL, HH, 0, 1);

    // 4) fixup: sum partials, split hi/lo, mirror lower triangle
    g_fixup<<<dim3(36, 4, B_), 256>>>(Gp, Gh, Gl);

    // 5) M^T = G W : A=G [H][H], B=W^T [n][k], K=H -> MT (bf16 split)
    gemm_mma<<<dim3(H_ / 128, H_ / 128, B_), 512, SMEM_BYTES>>>(
        Gh, Gl, wth, wtl, nullptr, MTh, MTl, H_, H_, H_, H_, HH, 0, HH, 1, 0);

    // 6) out = h M : A=h [L][H], B=MT [n][k], K=H -> fp32 out
    gemm_mma<<<dim3(H_ / 128, L_ / 128, B_), 512, SMEM_BYTES>>>(
        hh, hl, MTh, MTl, out, nullptr, nullptr, H_, H_, H_, H_, HL, HH, HL, 0, 0);
}